// round 6
// baseline (speedup 1.0000x reference)
#include <cuda_runtime.h>
#include <cstdint>

#define BATCH 4
#define SEQ   2048
#define DMODEL 1024
#define BS_ROWS (BATCH*SEQ)   // 8192
#define WSZ (DMODEL*DMODEL)

#define BM 128
#define BN 128
#define BKB 128                // int8 K elems (=bytes) per stage, 128B rows -> SW128
#define NTHREADS 256
#define STAGE_BYTES 65536      // Ahi 16K + Alo 16K + Bhi 16K + Blo 16K
#define SMEM_TOTAL (1024 + 2*STAGE_BYTES)

// ------------------------- scratch (device globals) -------------------------
__device__ int8_t g_Xhi[BS_ROWS*DMODEL], g_Xlo[BS_ROWS*DMODEL];
__device__ int8_t g_Whi[4*WSZ], g_Wlo[4*WSZ];
__device__ int8_t g_Qhi[BS_ROWS*DMODEL], g_Qlo[BS_ROWS*DMODEL];
__device__ int8_t g_Khi[BS_ROWS*DMODEL], g_Klo[BS_ROWS*DMODEL];
__device__ int8_t g_Vthi[(size_t)DMODEL*BS_ROWS], g_Vtlo[(size_t)DMODEL*BS_ROWS];
__device__ int8_t g_Ohi[BS_ROWS*DMODEL], g_Olo[BS_ROWS*DMODEL];
__device__ int8_t g_Phi[(size_t)BATCH*SEQ*SEQ], g_Plo[(size_t)BATCH*SEQ*SEQ];
__device__ float  g_Qf[BS_ROWS*DMODEL], g_Kf[BS_ROWS*DMODEL];
__device__ float  g_Vtf[(size_t)DMODEL*BS_ROWS], g_Of[BS_ROWS*DMODEL];
__device__ float  g_S[(size_t)BATCH*SEQ*SEQ];
// absmax slots: 0 X, 1 Wq, 2 Wk, 3 Wv, 4 Wo, 5 Q, 6 K, 7 Vt, 8 O, 9 P(const 2.0)
__device__ unsigned g_amax[16];

// ------------------------- PTX helpers -------------------------
__device__ __forceinline__ uint32_t smem_u32(const void* p) {
    uint32_t a;
    asm("{ .reg .u64 t; cvta.to.shared.u64 t, %1; cvt.u32.u64 %0, t; }" : "=r"(a) : "l"(p));
    return a;
}
__device__ __forceinline__ uint32_t swz(uint32_t o) { return o ^ ((o >> 3) & 0x70); }

__device__ __forceinline__ void cp16(uint32_t s, const void* g) {
    asm volatile("cp.async.cg.shared.global [%0], [%1], 16;" :: "r"(s), "l"(g) : "memory");
}
__device__ __forceinline__ void cp_commit() { asm volatile("cp.async.commit_group;" ::: "memory"); }
__device__ __forceinline__ void cp_wait0()  { asm volatile("cp.async.wait_group 0;" ::: "memory"); }
__device__ __forceinline__ void cp_wait1()  { asm volatile("cp.async.wait_group 1;" ::: "memory"); }

__device__ __forceinline__ void ldsm4(uint32_t* r, uint32_t addr) {
    asm volatile("ldmatrix.sync.aligned.m8n8.x4.shared.b16 {%0,%1,%2,%3}, [%4];"
                 : "=r"(r[0]), "=r"(r[1]), "=r"(r[2]), "=r"(r[3]) : "r"(addr));
}
__device__ __forceinline__ void imma(int* d, const uint32_t* a, const uint32_t* b) {
    asm volatile(
        "mma.sync.aligned.m16n8k32.row.col.s32.s8.s8.s32 "
        "{%0,%1,%2,%3}, {%4,%5,%6,%7}, {%8,%9}, {%0,%1,%2,%3};"
        : "+r"(d[0]), "+r"(d[1]), "+r"(d[2]), "+r"(d[3])
        : "r"(a[0]), "r"(a[1]), "r"(a[2]), "r"(a[3]), "r"(b[0]), "r"(b[1]));
}

__device__ __forceinline__ void quant_one(float x, float inv, int8_t& h, int8_t& l) {
    float q  = x * inv;
    float qh = rintf(q);
    qh = fminf(127.f, fmaxf(-127.f, qh));
    float ql = rintf((q - qh) * 254.f);
    ql = fminf(127.f, fmaxf(-127.f, ql));
    h = (int8_t)qh;
    l = (int8_t)ql;
}

// ------------------------- init scales -------------------------
__global__ void init_scales() {
    if (threadIdx.x < 16)
        g_amax[threadIdx.x] = (threadIdx.x == 9) ? __float_as_uint(2.0f) : 0u;
}

// ------------------------- absmax of X + 4 weights -------------------------
__global__ void __launch_bounds__(256)
absmax_multi(const float* __restrict__ X,
             const float* __restrict__ w0, const float* __restrict__ w1,
             const float* __restrict__ w2, const float* __restrict__ w3)
{
    const int seg = blockIdx.y;
    const float* s;
    int n4;
    if (seg == 0)      { s = X;  n4 = BS_ROWS * DMODEL / 4; }
    else if (seg == 1) { s = w0; n4 = WSZ / 4; }
    else if (seg == 2) { s = w1; n4 = WSZ / 4; }
    else if (seg == 3) { s = w2; n4 = WSZ / 4; }
    else               { s = w3; n4 = WSZ / 4; }

    float m = 0.f;
    for (int i = blockIdx.x * 256 + threadIdx.x; i < n4; i += gridDim.x * 256) {
        float4 t = ((const float4*)s)[i];
        m = fmaxf(m, fmaxf(fmaxf(fabsf(t.x), fabsf(t.y)), fmaxf(fabsf(t.z), fabsf(t.w))));
    }
#pragma unroll
    for (int o = 16; o > 0; o >>= 1) m = fmaxf(m, __shfl_xor_sync(0xffffffffu, m, o));
    __shared__ float red[8];
    if ((threadIdx.x & 31) == 0) red[threadIdx.x >> 5] = m;
    __syncthreads();
    if (threadIdx.x == 0) {
        float mm = red[0];
#pragma unroll
        for (int i = 1; i < 8; i++) mm = fmaxf(mm, red[i]);
        atomicMax(&g_amax[seg], __float_as_uint(mm));
    }
}

// ------------------------- quantize fp32 -> int8 hi/lo -------------------------
__global__ void __launch_bounds__(256)
quant_f32(const float* __restrict__ src, int8_t* __restrict__ hi,
          int8_t* __restrict__ lo, int n4, int slot)
{
    int i = blockIdx.x * blockDim.x + threadIdx.x;
    if (i >= n4) return;
    const float inv = 127.f / __uint_as_float(g_amax[slot]);
    float4 t = ((const float4*)src)[i];
    char4 h, l;
    quant_one(t.x, inv, (int8_t&)h.x, (int8_t&)l.x);
    quant_one(t.y, inv, (int8_t&)h.y, (int8_t&)l.y);
    quant_one(t.z, inv, (int8_t&)h.z, (int8_t&)l.z);
    quant_one(t.w, inv, (int8_t&)h.w, (int8_t&)l.w);
    ((char4*)hi)[i] = h;
    ((char4*)lo)[i] = l;
}

// ------------------------- GEMM: C = alpha*sA*sB*(A@B^T) (+bias) -------------------------
// A: [M,K] K-major int8 hi/lo (lda), B: [N,K] K-major int8 hi/lo (ldb).
// BIAS_MODE: 0 none, 1 per-col, 2 per-row. AMAX: atomicMax |C| into g_amax[slotOut].
// CTA 128x128, 8 warps (2 m x 4 n), warp tile 64x32.
template<int BIAS_MODE, bool AMAX>
__global__ void __launch_bounds__(NTHREADS, 1)
gemm_imma(const int8_t* __restrict__ Ahi, const int8_t* __restrict__ Alo,
          int lda, long long sA,
          const int8_t* __restrict__ Bhi, const int8_t* __restrict__ Blo,
          int ldb, long long sB,
          float* __restrict__ C, int ldc, long long sC,
          int Kdim, float alpha, const float* __restrict__ bias,
          int slotA, int slotB, int slotOut)
{
    extern __shared__ char smem_raw[];
    const uint32_t su = (smem_u32(smem_raw) + 1023u) & ~1023u;

    const int tid = threadIdx.x, lane = tid & 31, wid = tid >> 5;
    const int warp_m = wid >> 2;   // 0..1
    const int warp_n = wid & 3;    // 0..3
    const int m0 = blockIdx.y * BM, n0 = blockIdx.x * BN;
    const int z = blockIdx.z;

    Ahi += (size_t)z * sA;  Alo += (size_t)z * sA;
    Bhi += (size_t)z * sB;  Blo += (size_t)z * sB;
    C   += (size_t)z * sC;

    int acch[4][4][4], accc[4][4][4];
#pragma unroll
    for (int i = 0; i < 4; i++)
#pragma unroll
        for (int j = 0; j < 4; j++)
#pragma unroll
            for (int r = 0; r < 4; r++) { acch[i][j][r] = 0; accc[i][j][r] = 0; }

    auto load_stage = [&](int buf, int kt) {
        const uint32_t base = su + buf * STAGE_BYTES;
        const int8_t* gAh = Ahi + (size_t)m0 * lda + kt;
        const int8_t* gAl = Alo + (size_t)m0 * lda + kt;
        const int8_t* gBh = Bhi + (size_t)n0 * ldb + kt;
        const int8_t* gBl = Blo + (size_t)n0 * ldb + kt;
#pragma unroll
        for (int i = 0; i < 4; i++) {
            int u = tid + i * NTHREADS;          // 0..1023
            int r = u >> 3, eb = (u & 7) * 16;   // row 0..127, byte 0..112
            uint32_t so = swz((uint32_t)(r * 128 + eb));
            cp16(base +         so, gAh + (size_t)r * lda + eb);
            cp16(base + 16384 + so, gAl + (size_t)r * lda + eb);
            cp16(base + 32768 + so, gBh + (size_t)r * ldb + eb);
            cp16(base + 49152 + so, gBl + (size_t)r * ldb + eb);
        }
        cp_commit();
    };

    // ldmatrix lane address components (int8: k-chunk = 32 bytes per mma)
    const int arow = warp_m * 64 + (lane & 7) + ((lane >> 3) & 1) * 8;   // + mi*16
    const int achk = ((lane >> 4) & 1) * 16;
    const int brow = warp_n * 32 + (lane & 7) + ((lane >> 4) & 1) * 8;   // + nj2*16
    const int bchk = ((lane >> 3) & 1) * 16;

    auto compute = [&](int buf) {
        const uint32_t aAh = su + buf * STAGE_BYTES;
        const uint32_t aAl = aAh + 16384;
        const uint32_t aBh = aAh + 32768;
        const uint32_t aBl = aAh + 49152;
#pragma unroll
        for (int k32 = 0; k32 < 4; k32++) {
            const uint32_t kbA = (uint32_t)(k32 * 32 + achk);
            const uint32_t kbB = (uint32_t)(k32 * 32 + bchk);
            uint32_t ah[4][4], al[4][4];
#pragma unroll
            for (int mi = 0; mi < 4; mi++) {
                uint32_t off = swz((uint32_t)((arow + mi * 16) * 128) + kbA);
                ldsm4(ah[mi], aAh + off);
                ldsm4(al[mi], aAl + off);
            }
            uint32_t bh[4][2], bl[4][2];
#pragma unroll
            for (int nj2 = 0; nj2 < 2; nj2++) {
                uint32_t off = swz((uint32_t)((brow + nj2 * 16) * 128) + kbB);
                uint32_t t[4];
                ldsm4(t, aBh + off);
                bh[nj2*2][0] = t[0]; bh[nj2*2][1] = t[1];
                bh[nj2*2+1][0] = t[2]; bh[nj2*2+1][1] = t[3];
                ldsm4(t, aBl + off);
                bl[nj2*2][0] = t[0]; bl[nj2*2][1] = t[1];
                bl[nj2*2+1][0] = t[2]; bl[nj2*2+1][1] = t[3];
            }
            // hh into acch; cross terms (hl then lh) into accc, term-major for ILP
#pragma unroll
            for (int mi = 0; mi < 4; mi++)
#pragma unroll
                for (int nj = 0; nj < 4; nj++)
                    imma(acch[mi][nj], ah[mi], bh[nj]);
#pragma unroll
            for (int mi = 0; mi < 4; mi++)
#pragma unroll
                for (int nj = 0; nj < 4; nj++)
                    imma(accc[mi][nj], ah[mi], bl[nj]);
#pragma unroll
            for (int mi = 0; mi < 4; mi++)
#pragma unroll
                for (int nj = 0; nj < 4; nj++)
                    imma(accc[mi][nj], al[mi], bh[nj]);
        }
    };

    const int NT = Kdim / BKB;
    load_stage(0, 0);
    for (int t = 0; t < NT; t++) {
        if (t + 1 < NT) { load_stage((t + 1) & 1, (t + 1) * BKB); cp_wait1(); }
        else            { cp_wait0(); }
        __syncthreads();
        compute(t & 1);
        __syncthreads();
    }

    // ---------------- epilogue ----------------
    const float sa = __uint_as_float(g_amax[slotA]) * (1.f / 127.f);
    const float sb = __uint_as_float(g_amax[slotB]) * (1.f / 127.f);
    const float sc = sa * sb * alpha;
    const int gl = lane >> 2, q = lane & 3;
    float localm = 0.f;
#pragma unroll
    for (int mi = 0; mi < 4; mi++) {
#pragma unroll
        for (int nj = 0; nj < 4; nj++) {
            const int n = n0 + warp_n * 32 + nj * 8 + q * 2;
            float bcol0 = 0.f, bcol1 = 0.f;
            if (BIAS_MODE == 1) { bcol0 = bias[n]; bcol1 = bias[n + 1]; }
#pragma unroll
            for (int h = 0; h < 2; h++) {
                const int m = m0 + warp_m * 64 + mi * 16 + gl + h * 8;
                float v0 = ((float)acch[mi][nj][2*h+0] + (float)accc[mi][nj][2*h+0] * (1.f/254.f)) * sc;
                float v1 = ((float)acch[mi][nj][2*h+1] + (float)accc[mi][nj][2*h+1] * (1.f/254.f)) * sc;
                if (BIAS_MODE == 1) { v0 += bcol0; v1 += bcol1; }
                if (BIAS_MODE == 2) { float bb = bias[m]; v0 += bb; v1 += bb; }
                *(float2*)(C + (size_t)m * ldc + n) = make_float2(v0, v1);
                if (AMAX) localm = fmaxf(localm, fmaxf(fabsf(v0), fabsf(v1)));
            }
        }
    }
    if (AMAX) {
#pragma unroll
        for (int o = 16; o > 0; o >>= 1)
            localm = fmaxf(localm, __shfl_xor_sync(0xffffffffu, localm, o));
        __syncthreads();
        float* red = (float*)smem_raw;
        if (lane == 0) red[wid] = localm;
        __syncthreads();
        if (tid == 0) {
            float mm = red[0];
#pragma unroll
            for (int i = 1; i < 8; i++) mm = fmaxf(mm, red[i]);
            atomicMax(&g_amax[slotOut], __float_as_uint(mm));
        }
    }
}

// ------------------------- softmax + intensity, fused int8 quant out -------------------------
// attn = softmax(row) + intensity in [0,2) -> fixed scale 2/127
__global__ void __launch_bounds__(256)
softmax_quant(const float* __restrict__ S, const float* __restrict__ inten,
              int8_t* __restrict__ Phi, int8_t* __restrict__ Plo)
{
    const size_t row = blockIdx.x;
    const float* sr = S + row * SEQ;
    const float* ir = inten + row * SEQ;
    const int tid = threadIdx.x;
    const int base = tid * 8;

    float v[8];
    *(float4*)&v[0] = *(const float4*)(sr + base);
    *(float4*)&v[4] = *(const float4*)(sr + base + 4);
    float mx = v[0];
#pragma unroll
    for (int i = 1; i < 8; i++) mx = fmaxf(mx, v[i]);
    __shared__ float red[8];
#pragma unroll
    for (int o = 16; o > 0; o >>= 1)
        mx = fmaxf(mx, __shfl_xor_sync(0xffffffffu, mx, o));
    if ((tid & 31) == 0) red[tid >> 5] = mx;
    __syncthreads();
    mx = red[0];
#pragma unroll
    for (int i = 1; i < 8; i++) mx = fmaxf(mx, red[i]);
    __syncthreads();

    float sum = 0.f;
#pragma unroll
    for (int i = 0; i < 8; i++) {
        v[i] = expf(v[i] - mx);
        sum += v[i];
    }
#pragma unroll
    for (int o = 16; o > 0; o >>= 1)
        sum += __shfl_xor_sync(0xffffffffu, sum, o);
    if ((tid & 31) == 0) red[tid >> 5] = sum;
    __syncthreads();
    sum = 0.f;
#pragma unroll
    for (int i = 0; i < 8; i++) sum += red[i];
    const float inv = 1.f / sum;

    float w[8];
    *(float4*)&w[0] = *(const float4*)(ir + base);
    *(float4*)&w[4] = *(const float4*)(ir + base + 4);

    char4 h0, h1, l0, l1;
    const float qs = 63.5f;  // 127 / 2.0
    quant_one(v[0]*inv + w[0], qs, (int8_t&)h0.x, (int8_t&)l0.x);
    quant_one(v[1]*inv + w[1], qs, (int8_t&)h0.y, (int8_t&)l0.y);
    quant_one(v[2]*inv + w[2], qs, (int8_t&)h0.z, (int8_t&)l0.z);
    quant_one(v[3]*inv + w[3], qs, (int8_t&)h0.w, (int8_t&)l0.w);
    quant_one(v[4]*inv + w[4], qs, (int8_t&)h1.x, (int8_t&)l1.x);
    quant_one(v[5]*inv + w[5], qs, (int8_t&)h1.y, (int8_t&)l1.y);
    quant_one(v[6]*inv + w[6], qs, (int8_t&)h1.z, (int8_t&)l1.z);
    quant_one(v[7]*inv + w[7], qs, (int8_t&)h1.w, (int8_t&)l1.w);

    const size_t gb = row * SEQ + base;
    *(char4*)(Phi + gb)     = h0;
    *(char4*)(Phi + gb + 4) = h1;
    *(char4*)(Plo + gb)     = l0;
    *(char4*)(Plo + gb + 4) = l1;
}

// ------------------------- launch -------------------------
extern "C" void kernel_launch(void* const* d_in, const int* in_sizes, int n_in,
                              void* d_out, int out_size)
{
    const float* X  = (const float*)d_in[0];
    const float* I  = (const float*)d_in[1];
    const float* Wq = (const float*)d_in[2];
    const float* bq = (const float*)d_in[3];
    const float* Wk = (const float*)d_in[4];
    const float* bk = (const float*)d_in[5];
    const float* Wv = (const float*)d_in[6];
    const float* bv = (const float*)d_in[7];
    const float* Wo = (const float*)d_in[8];
    const float* bo = (const float*)d_in[9];
    float* out = (float*)d_out;

    int8_t *Xhi, *Xlo, *Whi, *Wlo, *Qhi, *Qlo, *Khi, *Klo;
    int8_t *Vthi, *Vtlo, *Ohi, *Olo, *Phi, *Plo;
    float *Qf, *Kf, *Vtf, *Of, *Sc;
    cudaGetSymbolAddress((void**)&Xhi,  g_Xhi);
    cudaGetSymbolAddress((void**)&Xlo,  g_Xlo);
    cudaGetSymbolAddress((void**)&Whi,  g_Whi);
    cudaGetSymbolAddress((void**)&Wlo,  g_Wlo);
    cudaGetSymbolAddress((void**)&Qhi,  g_Qhi);
    cudaGetSymbolAddress((void**)&Qlo,  g_Qlo);
    cudaGetSymbolAddress((void**)&Khi,  g_Khi);
    cudaGetSymbolAddress((void**)&Klo,  g_Klo);
    cudaGetSymbolAddress((void**)&Vthi, g_Vthi);
    cudaGetSymbolAddress((void**)&Vtlo, g_Vtlo);
    cudaGetSymbolAddress((void**)&Ohi,  g_Ohi);
    cudaGetSymbolAddress((void**)&Olo,  g_Olo);
    cudaGetSymbolAddress((void**)&Phi,  g_Phi);
    cudaGetSymbolAddress((void**)&Plo,  g_Plo);
    cudaGetSymbolAddress((void**)&Qf,   g_Qf);
    cudaGetSymbolAddress((void**)&Kf,   g_Kf);
    cudaGetSymbolAddress((void**)&Vtf,  g_Vtf);
    cudaGetSymbolAddress((void**)&Of,   g_Of);
    cudaGetSymbolAddress((void**)&Sc,   g_S);

    cudaFuncSetAttribute(gemm_imma<1, true>,  cudaFuncAttributeMaxDynamicSharedMemorySize, SMEM_TOTAL);
    cudaFuncSetAttribute(gemm_imma<2, true>,  cudaFuncAttributeMaxDynamicSharedMemorySize, SMEM_TOTAL);
    cudaFuncSetAttribute(gemm_imma<0, false>, cudaFuncAttributeMaxDynamicSharedMemorySize, SMEM_TOTAL);
    cudaFuncSetAttribute(gemm_imma<0, true>,  cudaFuncAttributeMaxDynamicSharedMemorySize, SMEM_TOTAL);
    cudaFuncSetAttribute(gemm_imma<1, false>, cudaFuncAttributeMaxDynamicSharedMemorySize, SMEM_TOTAL);

    const int XN4 = BS_ROWS * DMODEL / 4;   // 2,097,152
    const int WN4 = WSZ / 4;                // 262,144

    // 0. reset scales
    init_scales<<<1, 32>>>();
    // 1. absmax of inputs
    absmax_multi<<<dim3(128, 5), 256>>>(X, Wq, Wk, Wv, Wo);
    // 2. quantize inputs
    quant_f32<<<(XN4 + 255) / 256, 256>>>(X,  Xhi, Xlo, XN4, 0);
    quant_f32<<<(WN4 + 255) / 256, 256>>>(Wq, Whi + 0*WSZ, Wlo + 0*WSZ, WN4, 1);
    quant_f32<<<(WN4 + 255) / 256, 256>>>(Wk, Whi + 1*WSZ, Wlo + 1*WSZ, WN4, 2);
    quant_f32<<<(WN4 + 255) / 256, 256>>>(Wv, Whi + 2*WSZ, Wlo + 2*WSZ, WN4, 3);
    quant_f32<<<(WN4 + 255) / 256, 256>>>(Wo, Whi + 3*WSZ, Wlo + 3*WSZ, WN4, 4);

    dim3 blk(NTHREADS);

    // 3. Q = X@Wq^T + bq (fp32 + amax slot5)
    dim3 gP(DMODEL / BN, BS_ROWS / BM, 1);  // (8, 64)
    gemm_imma<1, true><<<gP, blk, SMEM_TOTAL>>>(
        Xhi, Xlo, DMODEL, 0, Whi + 0*WSZ, Wlo + 0*WSZ, DMODEL, 0,
        Qf, DMODEL, 0, DMODEL, 1.f, bq, 0, 1, 5);
    // 4. K (slot6)
    gemm_imma<1, true><<<gP, blk, SMEM_TOTAL>>>(
        Xhi, Xlo, DMODEL, 0, Whi + 1*WSZ, Wlo + 1*WSZ, DMODEL, 0,
        Kf, DMODEL, 0, DMODEL, 1.f, bk, 0, 2, 6);
    // 5. V^T = Wv@X^T + bv(row) (fp32 Vt [D, B*S], slot7)
    dim3 gV(BS_ROWS / BN, DMODEL / BM, 1);  // (64, 8)
    gemm_imma<2, true><<<gV, blk, SMEM_TOTAL>>>(
        Whi + 2*WSZ, Wlo + 2*WSZ, DMODEL, 0, Xhi, Xlo, DMODEL, 0,
        Vtf, BS_ROWS, 0, DMODEL, 1.f, bv, 3, 0, 7);
    // 6. quantize Q, K, Vt
    quant_f32<<<(XN4 + 255) / 256, 256>>>(Qf,  Qhi,  Qlo,  XN4, 5);
    quant_f32<<<(XN4 + 255) / 256, 256>>>(Kf,  Khi,  Klo,  XN4, 6);
    quant_f32<<<(XN4 + 255) / 256, 256>>>(Vtf, Vthi, Vtlo, XN4, 7);
    // 7. scores = (Q K^T)/32 -> fp32, batched
    dim3 gS(SEQ / BN, SEQ / BM, BATCH);     // (16, 16, 4)
    gemm_imma<0, false><<<gS, blk, SMEM_TOTAL>>>(
        Qhi, Qlo, DMODEL, (long long)SEQ * DMODEL,
        Khi, Klo, DMODEL, (long long)SEQ * DMODEL,
        Sc, SEQ, (long long)SEQ * SEQ, DMODEL, 0.03125f, nullptr, 5, 6, 0);
    // 8. attn = softmax + intensity -> int8 (fixed scale 2/127, slot9)
    softmax_quant<<<BATCH * SEQ, 256>>>(Sc, I, Phi, Plo);
    // 9. O = attn @ Vt^T (fp32 + amax slot8), batched
    dim3 gO(DMODEL / BN, SEQ / BM, BATCH);  // (8, 16, 4)
    gemm_imma<0, true><<<gO, blk, SMEM_TOTAL>>>(
        Phi, Plo, SEQ, (long long)SEQ * SEQ,
        Vthi, Vtlo, BS_ROWS, (long long)SEQ,
        Of, DMODEL, (long long)SEQ * DMODEL, SEQ, 1.f, nullptr, 9, 7, 8);
    // 10. quantize O
    quant_f32<<<(XN4 + 255) / 256, 256>>>(Of, Ohi, Olo, XN4, 8);
    // 11. out = O @ Wo^T + bo -> fp32
    gemm_imma<1, false><<<gP, blk, SMEM_TOTAL>>>(
        Ohi, Olo, DMODEL, 0, Whi + 3*WSZ, Wlo + 3*WSZ, DMODEL, 0,
        out, DMODEL, 0, DMODEL, 1.f, bo, 8, 4, 0);
}

// round 7
// speedup vs baseline: 4.9933x; 4.9933x over previous
#include <cuda_runtime.h>
#include <cuda_fp16.h>
#include <cstdint>

#define BATCH 4
#define SEQ   2048
#define DMODEL 1024
#define BS_ROWS (BATCH*SEQ)   // 8192
#define WSZ (DMODEL*DMODEL)

#define BM 128
#define BN 128
#define BKE 64                 // fp16 K elems per stage (128B rows, SW128)
#define NTHREADS 256
#define STAGE_BYTES 49152      // Ah 16K + Al 16K + Bh 16K
#define SMEM_TOTAL (1024 + 2*STAGE_BYTES)

// ------------------------- scratch (device globals) -------------------------
__device__ __half g_Xh[BS_ROWS*DMODEL];
__device__ __half g_Wqh[WSZ], g_Wkh[WSZ], g_Woh[WSZ];
__device__ __half g_Wvh[WSZ], g_Wvl[WSZ];
__device__ __half g_Qh[BS_ROWS*DMODEL], g_Kh[BS_ROWS*DMODEL];
__device__ __half g_Vth[(size_t)DMODEL*BS_ROWS];
__device__ __half g_Ohi[BS_ROWS*DMODEL], g_Olo[BS_ROWS*DMODEL];
__device__ __half g_Phi[(size_t)BATCH*SEQ*SEQ], g_Plo[(size_t)BATCH*SEQ*SEQ];
__device__ float  g_S[(size_t)BATCH*SEQ*SEQ];

// ------------------------- PTX helpers -------------------------
__device__ __forceinline__ uint32_t smem_u32(const void* p) {
    uint32_t a;
    asm("{ .reg .u64 t; cvta.to.shared.u64 t, %1; cvt.u32.u64 %0, t; }" : "=r"(a) : "l"(p));
    return a;
}
__device__ __forceinline__ uint32_t swz(uint32_t o) { return o ^ ((o >> 3) & 0x70); }

__device__ __forceinline__ void cp16(uint32_t s, const void* g) {
    asm volatile("cp.async.cg.shared.global [%0], [%1], 16;" :: "r"(s), "l"(g) : "memory");
}
__device__ __forceinline__ void cp_commit() { asm volatile("cp.async.commit_group;" ::: "memory"); }
__device__ __forceinline__ void cp_wait0()  { asm volatile("cp.async.wait_group 0;" ::: "memory"); }
__device__ __forceinline__ void cp_wait1()  { asm volatile("cp.async.wait_group 1;" ::: "memory"); }

__device__ __forceinline__ void ldsm4(uint32_t* r, uint32_t addr) {
    asm volatile("ldmatrix.sync.aligned.m8n8.x4.shared.b16 {%0,%1,%2,%3}, [%4];"
                 : "=r"(r[0]), "=r"(r[1]), "=r"(r[2]), "=r"(r[3]) : "r"(addr));
}
__device__ __forceinline__ void mma_fp16(float* d, const uint32_t* a, const uint32_t* b) {
    asm volatile(
        "mma.sync.aligned.m16n8k16.row.col.f32.f16.f16.f32 "
        "{%0,%1,%2,%3}, {%4,%5,%6,%7}, {%8,%9}, {%0,%1,%2,%3};"
        : "+f"(d[0]), "+f"(d[1]), "+f"(d[2]), "+f"(d[3])
        : "r"(a[0]), "r"(a[1]), "r"(a[2]), "r"(a[3]), "r"(b[0]), "r"(b[1]));
}

__device__ __forceinline__ void split1(float x, __half& h, __half& l) {
    h = __float2half(x);
    l = __float2half(x - __half2float(h));
}
__device__ __forceinline__ uint32_t pack_h2(__half a, __half b) {
    __half2 p; p.x = a; p.y = b;
    return *(uint32_t*)&p;
}

// ------------------------- GEMM -------------------------
// C = alpha * A @ B^T (+bias); A [M,K] K-major fp16 hi(/lo), B [N,K] K-major fp16.
// NTERMS: 1 = Ah*Bh; 2 = Ah*Bh + Al*Bh (A split exact, B single-rounded).
// OUT: 0 fp32 -> Cf; 1 fp16 -> Ch; 2 fp16 split -> Ch + Cl.
// BIAS_MODE: 0 none, 1 per-col(n), 2 per-row(m).
// CTA 128x128, 8 warps (2m x 4n), warp tile 64x32.
template<int NTERMS, int OUT, int BIAS_MODE>
__global__ void __launch_bounds__(NTHREADS, 1)
gemm_fp16(const __half* __restrict__ Ahi, const __half* __restrict__ Alo,
          int lda, long long sA,
          const __half* __restrict__ Bh, int ldb, long long sB,
          float* __restrict__ Cf, __half* __restrict__ Ch, __half* __restrict__ Cl,
          int ldc, long long sC,
          int Kdim, float alpha, const float* __restrict__ bias)
{
    extern __shared__ char smem_raw[];
    const uint32_t su = (smem_u32(smem_raw) + 1023u) & ~1023u;

    const int tid = threadIdx.x, lane = tid & 31, wid = tid >> 5;
    const int warp_m = wid >> 2;   // 0..1
    const int warp_n = wid & 3;    // 0..3
    const int m0 = blockIdx.y * BM, n0 = blockIdx.x * BN;
    const int z = blockIdx.z;

    Ahi += (size_t)z * sA;
    if (NTERMS == 2) Alo += (size_t)z * sA;
    Bh += (size_t)z * sB;
    if (OUT == 0) Cf += (size_t)z * sC;
    else { Ch += (size_t)z * sC; if (OUT == 2) Cl += (size_t)z * sC; }

    float acc[4][4][4];
#pragma unroll
    for (int i = 0; i < 4; i++)
#pragma unroll
        for (int j = 0; j < 4; j++)
#pragma unroll
            for (int r = 0; r < 4; r++) acc[i][j][r] = 0.f;

    auto load_stage = [&](int buf, int kt) {
        const uint32_t base = su + buf * STAGE_BYTES;
        const __half* gAh = Ahi + (size_t)m0 * lda + kt;
        const __half* gBh = Bh  + (size_t)n0 * ldb + kt;
#pragma unroll
        for (int i = 0; i < 4; i++) {
            int u = tid + i * NTHREADS;          // 0..1023
            int r = u >> 3, eb = (u & 7) * 16;   // row 0..127, byte 0..112
            uint32_t so = swz((uint32_t)(r * 128 + eb));
            cp16(base +         so, gAh + (size_t)r * lda + (eb >> 1));
            cp16(base + 32768 + so, gBh + (size_t)r * ldb + (eb >> 1));
        }
        if (NTERMS == 2) {
            const __half* gAl = Alo + (size_t)m0 * lda + kt;
#pragma unroll
            for (int i = 0; i < 4; i++) {
                int u = tid + i * NTHREADS;
                int r = u >> 3, eb = (u & 7) * 16;
                uint32_t so = swz((uint32_t)(r * 128 + eb));
                cp16(base + 16384 + so, gAl + (size_t)r * lda + (eb >> 1));
            }
        }
        cp_commit();
    };

    // ldmatrix lane address components
    const int arow = warp_m * 64 + (lane & 7) + ((lane >> 3) & 1) * 8;   // + mi*16
    const int achk = (lane >> 4) * 16;                                    // k byte
    const int brow = warp_n * 32 + (lane & 7) + ((lane >> 4) & 1) * 8;   // + nj2*16
    const int bchk = ((lane >> 3) & 1) * 16;

    auto compute = [&](int buf) {
        const uint32_t aAh = su + buf * STAGE_BYTES;
        const uint32_t aAl = aAh + 16384;
        const uint32_t aBh = aAh + 32768;
#pragma unroll
        for (int k16 = 0; k16 < 4; k16++) {
            const uint32_t kbA = (uint32_t)(k16 * 32 + achk);
            const uint32_t kbB = (uint32_t)(k16 * 32 + bchk);
            uint32_t ah[4][4], al[4][4];
#pragma unroll
            for (int mi = 0; mi < 4; mi++) {
                uint32_t off = swz((uint32_t)((arow + mi * 16) * 128) + kbA);
                ldsm4(ah[mi], aAh + off);
                if (NTERMS == 2) ldsm4(al[mi], aAl + off);
            }
            uint32_t bh[4][2];
#pragma unroll
            for (int nj2 = 0; nj2 < 2; nj2++) {
                uint32_t off = swz((uint32_t)((brow + nj2 * 16) * 128) + kbB);
                uint32_t t[4];
                ldsm4(t, aBh + off);
                bh[nj2*2][0] = t[0]; bh[nj2*2][1] = t[1];
                bh[nj2*2+1][0] = t[2]; bh[nj2*2+1][1] = t[3];
            }
            // term-major: 16 independent accumulators between same-acc reuses
#pragma unroll
            for (int mi = 0; mi < 4; mi++)
#pragma unroll
                for (int nj = 0; nj < 4; nj++)
                    mma_fp16(acc[mi][nj], ah[mi], bh[nj]);
            if (NTERMS == 2) {
#pragma unroll
                for (int mi = 0; mi < 4; mi++)
#pragma unroll
                    for (int nj = 0; nj < 4; nj++)
                        mma_fp16(acc[mi][nj], al[mi], bh[nj]);
            }
        }
    };

    const int NT = Kdim / BKE;
    load_stage(0, 0);
    for (int t = 0; t < NT; t++) {
        if (t + 1 < NT) { load_stage((t + 1) & 1, (t + 1) * BKE); cp_wait1(); }
        else            { cp_wait0(); }
        __syncthreads();
        compute(t & 1);
        __syncthreads();
    }

    // ---------------- epilogue ----------------
    const int gl = lane >> 2, q = lane & 3;
#pragma unroll
    for (int mi = 0; mi < 4; mi++) {
#pragma unroll
        for (int nj = 0; nj < 4; nj++) {
            const int n = n0 + warp_n * 32 + nj * 8 + q * 2;
            float bcol0 = 0.f, bcol1 = 0.f;
            if (BIAS_MODE == 1) { bcol0 = bias[n]; bcol1 = bias[n + 1]; }
#pragma unroll
            for (int h = 0; h < 2; h++) {
                const int m = m0 + warp_m * 64 + mi * 16 + gl + h * 8;
                float v0 = acc[mi][nj][2 * h + 0] * alpha;
                float v1 = acc[mi][nj][2 * h + 1] * alpha;
                if (BIAS_MODE == 1) { v0 += bcol0; v1 += bcol1; }
                if (BIAS_MODE == 2) { float bb = bias[m]; v0 += bb; v1 += bb; }
                const size_t gidx = (size_t)m * ldc + n;
                if (OUT == 0) {
                    *(float2*)(Cf + gidx) = make_float2(v0, v1);
                } else if (OUT == 1) {
                    *(uint32_t*)(Ch + gidx) = pack_h2(__float2half(v0), __float2half(v1));
                } else {
                    __half h0, h1, l0, l1;
                    split1(v0, h0, l0); split1(v1, h1, l1);
                    *(uint32_t*)(Ch + gidx) = pack_h2(h0, h1);
                    *(uint32_t*)(Cl + gidx) = pack_h2(l0, l1);
                }
            }
        }
    }
}

// ------------------------- fp32 -> fp16 (single) -------------------------
__global__ void __launch_bounds__(256)
conv_f16(const float* __restrict__ x, __half* __restrict__ h, int n4)
{
    int i = blockIdx.x * blockDim.x + threadIdx.x;
    if (i >= n4) return;
    float4 t = ((const float4*)x)[i];
    uint2 hv;
    hv.x = pack_h2(__float2half(t.x), __float2half(t.y));
    hv.y = pack_h2(__float2half(t.z), __float2half(t.w));
    ((uint2*)h)[i] = hv;
}

// ------------------------- fp32 -> fp16 hi/lo split -------------------------
__global__ void __launch_bounds__(256)
split_f16(const float* __restrict__ x, __half* __restrict__ hi,
          __half* __restrict__ lo, int n4)
{
    int i = blockIdx.x * blockDim.x + threadIdx.x;
    if (i >= n4) return;
    float4 t = ((const float4*)x)[i];
    __half h0, h1, h2, h3, l0, l1, l2, l3;
    split1(t.x, h0, l0); split1(t.y, h1, l1);
    split1(t.z, h2, l2); split1(t.w, h3, l3);
    uint2 hv, lv;
    hv.x = pack_h2(h0, h1); hv.y = pack_h2(h2, h3);
    lv.x = pack_h2(l0, l1); lv.y = pack_h2(l2, l3);
    ((uint2*)hi)[i] = hv;
    ((uint2*)lo)[i] = lv;
}

// ------------------------- softmax + intensity, fused fp16 split out -------------------------
__global__ void __launch_bounds__(256)
softmax_split(const float* __restrict__ S, const float* __restrict__ inten,
              __half* __restrict__ Phi, __half* __restrict__ Plo)
{
    const size_t row = blockIdx.x;
    const float* sr = S + row * SEQ;
    const float* ir = inten + row * SEQ;
    const int tid = threadIdx.x;
    const int base = tid * 8;

    float v[8];
    *(float4*)&v[0] = *(const float4*)(sr + base);
    *(float4*)&v[4] = *(const float4*)(sr + base + 4);
    float mx = v[0];
#pragma unroll
    for (int i = 1; i < 8; i++) mx = fmaxf(mx, v[i]);
    __shared__ float red[8];
#pragma unroll
    for (int o = 16; o > 0; o >>= 1)
        mx = fmaxf(mx, __shfl_xor_sync(0xffffffffu, mx, o));
    if ((tid & 31) == 0) red[tid >> 5] = mx;
    __syncthreads();
    mx = red[0];
#pragma unroll
    for (int i = 1; i < 8; i++) mx = fmaxf(mx, red[i]);
    __syncthreads();

    float sum = 0.f;
#pragma unroll
    for (int i = 0; i < 8; i++) {
        v[i] = expf(v[i] - mx);
        sum += v[i];
    }
#pragma unroll
    for (int o = 16; o > 0; o >>= 1)
        sum += __shfl_xor_sync(0xffffffffu, sum, o);
    if ((tid & 31) == 0) red[tid >> 5] = sum;
    __syncthreads();
    sum = 0.f;
#pragma unroll
    for (int i = 0; i < 8; i++) sum += red[i];
    const float inv = 1.f / sum;

    float w[8];
    *(float4*)&w[0] = *(const float4*)(ir + base);
    *(float4*)&w[4] = *(const float4*)(ir + base + 4);

    __half h[8], l[8];
#pragma unroll
    for (int i = 0; i < 8; i++) split1(v[i] * inv + w[i], h[i], l[i]);

    const size_t gb = row * SEQ + base;
    uint2 hv, lv;
    hv.x = pack_h2(h[0], h[1]); hv.y = pack_h2(h[2], h[3]);
    lv.x = pack_h2(l[0], l[1]); lv.y = pack_h2(l[2], l[3]);
    *(uint2*)(Phi + gb) = hv;
    *(uint2*)(Plo + gb) = lv;
    hv.x = pack_h2(h[4], h[5]); hv.y = pack_h2(h[6], h[7]);
    lv.x = pack_h2(l[4], l[5]); lv.y = pack_h2(l[6], l[7]);
    *(uint2*)(Phi + gb + 4) = hv;
    *(uint2*)(Plo + gb + 4) = lv;
}

// ------------------------- launch -------------------------
extern "C" void kernel_launch(void* const* d_in, const int* in_sizes, int n_in,
                              void* d_out, int out_size)
{
    const float* X  = (const float*)d_in[0];
    const float* I  = (const float*)d_in[1];
    const float* Wq = (const float*)d_in[2];
    const float* bq = (const float*)d_in[3];
    const float* Wk = (const float*)d_in[4];
    const float* bk = (const float*)d_in[5];
    const float* Wv = (const float*)d_in[6];
    const float* bv = (const float*)d_in[7];
    const float* Wo = (const float*)d_in[8];
    const float* bo = (const float*)d_in[9];
    float* out = (float*)d_out;

    __half *Xh, *Wqh, *Wkh, *Woh, *Wvh, *Wvl, *Qh, *Kh, *Vth, *Ohi, *Olo, *Phi, *Plo;
    float* Sc;
    cudaGetSymbolAddress((void**)&Xh,  g_Xh);
    cudaGetSymbolAddress((void**)&Wqh, g_Wqh);
    cudaGetSymbolAddress((void**)&Wkh, g_Wkh);
    cudaGetSymbolAddress((void**)&Woh, g_Woh);
    cudaGetSymbolAddress((void**)&Wvh, g_Wvh);
    cudaGetSymbolAddress((void**)&Wvl, g_Wvl);
    cudaGetSymbolAddress((void**)&Qh,  g_Qh);
    cudaGetSymbolAddress((void**)&Kh,  g_Kh);
    cudaGetSymbolAddress((void**)&Vth, g_Vth);
    cudaGetSymbolAddress((void**)&Ohi, g_Ohi);
    cudaGetSymbolAddress((void**)&Olo, g_Olo);
    cudaGetSymbolAddress((void**)&Phi, g_Phi);
    cudaGetSymbolAddress((void**)&Plo, g_Plo);
    cudaGetSymbolAddress((void**)&Sc,  g_S);

    cudaFuncSetAttribute(gemm_fp16<1,1,1>, cudaFuncAttributeMaxDynamicSharedMemorySize, SMEM_TOTAL);
    cudaFuncSetAttribute(gemm_fp16<2,1,2>, cudaFuncAttributeMaxDynamicSharedMemorySize, SMEM_TOTAL);
    cudaFuncSetAttribute(gemm_fp16<1,0,0>, cudaFuncAttributeMaxDynamicSharedMemorySize, SMEM_TOTAL);
    cudaFuncSetAttribute(gemm_fp16<2,2,0>, cudaFuncAttributeMaxDynamicSharedMemorySize, SMEM_TOTAL);
    cudaFuncSetAttribute(gemm_fp16<2,0,1>, cudaFuncAttributeMaxDynamicSharedMemorySize, SMEM_TOTAL);

    const int XN4 = BS_ROWS * DMODEL / 4;
    const int WN4 = WSZ / 4;

    // 1. convert inputs
    conv_f16<<<(XN4 + 255) / 256, 256>>>(X,  Xh,  XN4);
    conv_f16<<<(WN4 + 255) / 256, 256>>>(Wq, Wqh, WN4);
    conv_f16<<<(WN4 + 255) / 256, 256>>>(Wk, Wkh, WN4);
    conv_f16<<<(WN4 + 255) / 256, 256>>>(Wo, Woh, WN4);
    split_f16<<<(WN4 + 255) / 256, 256>>>(Wv, Wvh, Wvl, WN4);

    dim3 blk(NTHREADS);

    // 2. Q = X@Wq^T + bq -> fp16 (1-term: precision damped by softmax path)
    dim3 gP(DMODEL / BN, BS_ROWS / BM, 1);  // (8, 64)
    gemm_fp16<1,1,1><<<gP, blk, SMEM_TOTAL>>>(
        Xh, nullptr, DMODEL, 0, Wqh, DMODEL, 0,
        nullptr, Qh, nullptr, DMODEL, 0, DMODEL, 1.f, bq);
    // 3. K -> fp16 (1-term)
    gemm_fp16<1,1,1><<<gP, blk, SMEM_TOTAL>>>(
        Xh, nullptr, DMODEL, 0, Wkh, DMODEL, 0,
        nullptr, Kh, nullptr, DMODEL, 0, DMODEL, 1.f, bk);
    // 4. V^T = Wv@X^T + bv(row) -> fp16, 2-term (Wv split), Vt[d, b*S+s] ld 8192
    dim3 gV(BS_ROWS / BN, DMODEL / BM, 1);  // (64, 8)
    gemm_fp16<2,1,2><<<gV, blk, SMEM_TOTAL>>>(
        Wvh, Wvl, DMODEL, 0, Xh, DMODEL, 0,
        nullptr, Vth, nullptr, BS_ROWS, 0, DMODEL, 1.f, bv);
    // 5. scores = (Q K^T)/32 -> fp32, 1-term, batched
    dim3 gS(SEQ / BN, SEQ / BM, BATCH);     // (16, 16, 4)
    gemm_fp16<1,0,0><<<gS, blk, SMEM_TOTAL>>>(
        Qh, nullptr, DMODEL, (long long)SEQ * DMODEL,
        Kh, DMODEL, (long long)SEQ * DMODEL,
        Sc, nullptr, nullptr, SEQ, (long long)SEQ * SEQ,
        DMODEL, 0.03125f, nullptr);
    // 6. attn = softmax + intensity -> fp16 hi/lo
    softmax_split<<<BATCH * SEQ, 256>>>(Sc, I, Phi, Plo);
    // 7. O = attn @ Vt^T -> fp16 split out, 2-term (attn split), batched
    dim3 gO(DMODEL / BN, SEQ / BM, BATCH);  // (8, 16, 4)
    gemm_fp16<2,2,0><<<gO, blk, SMEM_TOTAL>>>(
        Phi, Plo, SEQ, (long long)SEQ * SEQ,
        Vth, BS_ROWS, (long long)SEQ,
        nullptr, Ohi, Olo, DMODEL, (long long)SEQ * DMODEL,
        SEQ, 1.f, nullptr);
    // 8. out = O @ Wo^T + bo -> fp32, 2-term (O split)
    gemm_fp16<2,0,1><<<gP, blk, SMEM_TOTAL>>>(
        Ohi, Olo, DMODEL, 0, Woh, DMODEL, 0,
        out, nullptr, nullptr, DMODEL, 0, DMODEL, 1.f, bo);
}

// round 9
// speedup vs baseline: 6.7225x; 1.3463x over previous
#include <cuda_runtime.h>
#include <cuda_fp16.h>
#include <cstdint>

#define BATCH 4
#define SEQ   2048
#define DMODEL 1024
#define BS_ROWS (BATCH*SEQ)   // 8192
#define WSZ (DMODEL*DMODEL)

#define BM 128
#define BN 128
#define BKE 64                 // fp16 K elems per stage (128B rows, SW128)
#define NTHREADS 256
#define STAGE_BYTES 32768      // A 16K + B 16K
#define SMEM_TOTAL (1024 + 2*STAGE_BYTES)

// ------------------------- scratch (device globals) -------------------------
__device__ __half g_Xh[BS_ROWS*DMODEL];
__device__ __half g_Wc[4*WSZ];                       // [Wq, Wk, Wv, Wo]
__device__ __half g_QKh[2*BS_ROWS*DMODEL];           // [Q, K]
__device__ __half g_Vth[(size_t)DMODEL*BS_ROWS];
__device__ __half g_Oh[BS_ROWS*DMODEL];
__device__ __half g_Ph[(size_t)BATCH*SEQ*SEQ];
__device__ float  g_S[(size_t)BATCH*SEQ*SEQ];
__device__ float  g_bqk[2*DMODEL];

// ------------------------- PTX helpers -------------------------
__device__ __forceinline__ uint32_t smem_u32(const void* p) {
    uint32_t a;
    asm("{ .reg .u64 t; cvta.to.shared.u64 t, %1; cvt.u32.u64 %0, t; }" : "=r"(a) : "l"(p));
    return a;
}
__device__ __forceinline__ uint32_t swz(uint32_t o) { return o ^ ((o >> 3) & 0x70); }

__device__ __forceinline__ void cp16(uint32_t s, const void* g) {
    asm volatile("cp.async.cg.shared.global [%0], [%1], 16;" :: "r"(s), "l"(g) : "memory");
}
__device__ __forceinline__ void cp_commit() { asm volatile("cp.async.commit_group;" ::: "memory"); }
__device__ __forceinline__ void cp_wait0()  { asm volatile("cp.async.wait_group 0;" ::: "memory"); }
__device__ __forceinline__ void cp_wait1()  { asm volatile("cp.async.wait_group 1;" ::: "memory"); }

__device__ __forceinline__ void ldsm4(uint32_t* r, uint32_t addr) {
    asm volatile("ldmatrix.sync.aligned.m8n8.x4.shared.b16 {%0,%1,%2,%3}, [%4];"
                 : "=r"(r[0]), "=r"(r[1]), "=r"(r[2]), "=r"(r[3]) : "r"(addr));
}
__device__ __forceinline__ void mma_fp16(float* d, const uint32_t* a, const uint32_t* b) {
    asm volatile(
        "mma.sync.aligned.m16n8k16.row.col.f32.f16.f16.f32 "
        "{%0,%1,%2,%3}, {%4,%5,%6,%7}, {%8,%9}, {%0,%1,%2,%3};"
        : "+f"(d[0]), "+f"(d[1]), "+f"(d[2]), "+f"(d[3])
        : "r"(a[0]), "r"(a[1]), "r"(a[2]), "r"(a[3]), "r"(b[0]), "r"(b[1]));
}
__device__ __forceinline__ uint32_t pack_h2(__half a, __half b) {
    __half2 p; p.x = a; p.y = b;
    return *(uint32_t*)&p;
}

// ------------------------- GEMM (single-term fp16) -------------------------
// C = alpha * A @ B^T (+bias); A [M,K] K-major fp16 (lda), B [N,K] K-major fp16 (ldb).
// OUT: 0 fp32 -> Cf; 1 fp16 -> Ch.  BIAS_MODE: 0 none, 1 per-col(n), 2 per-row(m).
// CTA 128x128, 8 warps (2m x 4n), warp tile 64x32.
template<int OUT, int BIAS_MODE>
__global__ void __launch_bounds__(NTHREADS, 1)
gemm_fp16(const __half* __restrict__ A, int lda, long long sA,
          const __half* __restrict__ B, int ldb, long long sB,
          float* __restrict__ Cf, __half* __restrict__ Ch, int ldc, long long sC,
          int Kdim, float alpha, const float* __restrict__ bias, int sBias)
{
    extern __shared__ char smem_raw[];
    const uint32_t su = (smem_u32(smem_raw) + 1023u) & ~1023u;

    const int tid = threadIdx.x, lane = tid & 31, wid = tid >> 5;
    const int warp_m = wid >> 2;   // 0..1
    const int warp_n = wid & 3;    // 0..3
    const int m0 = blockIdx.y * BM, n0 = blockIdx.x * BN;
    const int z = blockIdx.z;

    A += (size_t)z * sA;
    B += (size_t)z * sB;
    if (OUT == 0) Cf += (size_t)z * sC; else Ch += (size_t)z * sC;
    if (BIAS_MODE) bias += (size_t)z * sBias;

    float acc[4][4][4];
#pragma unroll
    for (int i = 0; i < 4; i++)
#pragma unroll
        for (int j = 0; j < 4; j++)
#pragma unroll
            for (int r = 0; r < 4; r++) acc[i][j][r] = 0.f;

    auto load_stage = [&](int buf, int kt) {
        const uint32_t base = su + buf * STAGE_BYTES;
        const __half* gA = A + (size_t)m0 * lda + kt;
        const __half* gB = B + (size_t)n0 * ldb + kt;
#pragma unroll
        for (int i = 0; i < 4; i++) {
            int u = tid + i * NTHREADS;          // 0..1023
            int r = u >> 3, eb = (u & 7) * 16;   // row 0..127, byte 0..112
            uint32_t so = swz((uint32_t)(r * 128 + eb));
            cp16(base +         so, gA + (size_t)r * lda + (eb >> 1));
            cp16(base + 16384 + so, gB + (size_t)r * ldb + (eb >> 1));
        }
        cp_commit();
    };

    const int arow = warp_m * 64 + (lane & 7) + ((lane >> 3) & 1) * 8;   // + mi*16
    const int achk = (lane >> 4) * 16;
    const int brow = warp_n * 32 + (lane & 7) + ((lane >> 4) & 1) * 8;   // + nj2*16
    const int bchk = ((lane >> 3) & 1) * 16;

    auto compute = [&](int buf) {
        const uint32_t aA = su + buf * STAGE_BYTES;
        const uint32_t aB = aA + 16384;
#pragma unroll
        for (int k16 = 0; k16 < 4; k16++) {
            const uint32_t kbA = (uint32_t)(k16 * 32 + achk);
            const uint32_t kbB = (uint32_t)(k16 * 32 + bchk);
            uint32_t av[4][4];
#pragma unroll
            for (int mi = 0; mi < 4; mi++)
                ldsm4(av[mi], aA + swz((uint32_t)((arow + mi * 16) * 128) + kbA));
            uint32_t bv[4][2];
#pragma unroll
            for (int nj2 = 0; nj2 < 2; nj2++) {
                uint32_t t[4];
                ldsm4(t, aB + swz((uint32_t)((brow + nj2 * 16) * 128) + kbB));
                bv[nj2*2][0] = t[0]; bv[nj2*2][1] = t[1];
                bv[nj2*2+1][0] = t[2]; bv[nj2*2+1][1] = t[3];
            }
#pragma unroll
            for (int mi = 0; mi < 4; mi++)
#pragma unroll
                for (int nj = 0; nj < 4; nj++)
                    mma_fp16(acc[mi][nj], av[mi], bv[nj]);
        }
    };

    const int NT = Kdim / BKE;
    load_stage(0, 0);
    for (int t = 0; t < NT; t++) {
        if (t + 1 < NT) { load_stage((t + 1) & 1, (t + 1) * BKE); cp_wait1(); }
        else            { cp_wait0(); }
        __syncthreads();
        compute(t & 1);
        __syncthreads();
    }

    // ---------------- epilogue ----------------
    const int gl = lane >> 2, q = lane & 3;
#pragma unroll
    for (int mi = 0; mi < 4; mi++) {
#pragma unroll
        for (int nj = 0; nj < 4; nj++) {
            const int n = n0 + warp_n * 32 + nj * 8 + q * 2;
            float bcol0 = 0.f, bcol1 = 0.f;
            if (BIAS_MODE == 1) { bcol0 = bias[n]; bcol1 = bias[n + 1]; }
#pragma unroll
            for (int h = 0; h < 2; h++) {
                const int m = m0 + warp_m * 64 + mi * 16 + gl + h * 8;
                float v0 = acc[mi][nj][2 * h + 0] * alpha;
                float v1 = acc[mi][nj][2 * h + 1] * alpha;
                if (BIAS_MODE == 1) { v0 += bcol0; v1 += bcol1; }
                if (BIAS_MODE == 2) { float bb = bias[m]; v0 += bb; v1 += bb; }
                const size_t gidx = (size_t)m * ldc + n;
                if (OUT == 0)
                    *(float2*)(Cf + gidx) = make_float2(v0, v1);
                else
                    *(uint32_t*)(Ch + gidx) = pack_h2(__float2half(v0), __float2half(v1));
            }
        }
    }
}

// ------------------------- fp32 -> fp16 converts -------------------------
__global__ void __launch_bounds__(256)
conv_f16(const float* __restrict__ x, __half* __restrict__ h, int n4)
{
    int i = blockIdx.x * blockDim.x + threadIdx.x;
    if (i >= n4) return;
    float4 t = ((const float4*)x)[i];
    uint2 hv;
    hv.x = pack_h2(__float2half(t.x), __float2half(t.y));
    hv.y = pack_h2(__float2half(t.z), __float2half(t.w));
    ((uint2*)h)[i] = hv;
}

__global__ void __launch_bounds__(256)
conv4_f16(const float* __restrict__ w0, const float* __restrict__ w1,
          const float* __restrict__ w2, const float* __restrict__ w3,
          __half* __restrict__ dst)
{
    const int seg = blockIdx.y;
    const float* s = (seg == 0) ? w0 : (seg == 1) ? w1 : (seg == 2) ? w2 : w3;
    int i = blockIdx.x * blockDim.x + threadIdx.x;
    if (i >= WSZ / 4) return;
    float4 t = ((const float4*)s)[i];
    uint2 hv;
    hv.x = pack_h2(__float2half(t.x), __float2half(t.y));
    hv.y = pack_h2(__float2half(t.z), __float2half(t.w));
    ((uint2*)(dst + (size_t)seg * WSZ))[i] = hv;
}

// ------------------------- pack Q/K biases (capture-safe copy) -------------------------
__global__ void __launch_bounds__(256)
pack_bias(const float* __restrict__ bq, const float* __restrict__ bk,
          float* __restrict__ dst)
{
    int i = blockIdx.x * blockDim.x + threadIdx.x;
    if (i < DMODEL)          dst[i] = bq[i];
    else if (i < 2 * DMODEL) dst[i] = bk[i - DMODEL];
}

// ------------------------- softmax + intensity -> single fp16 -------------------------
__global__ void __launch_bounds__(256)
softmax_f16(const float* __restrict__ S, const float* __restrict__ inten,
            __half* __restrict__ P)
{
    const size_t row = blockIdx.x;
    const float* sr = S + row * SEQ;
    const float* ir = inten + row * SEQ;
    const int tid = threadIdx.x;
    const int base = tid * 8;

    float v[8];
    *(float4*)&v[0] = *(const float4*)(sr + base);
    *(float4*)&v[4] = *(const float4*)(sr + base + 4);
    float mx = v[0];
#pragma unroll
    for (int i = 1; i < 8; i++) mx = fmaxf(mx, v[i]);
    __shared__ float red[8];
#pragma unroll
    for (int o = 16; o > 0; o >>= 1)
        mx = fmaxf(mx, __shfl_xor_sync(0xffffffffu, mx, o));
    if ((tid & 31) == 0) red[tid >> 5] = mx;
    __syncthreads();
    mx = red[0];
#pragma unroll
    for (int i = 1; i < 8; i++) mx = fmaxf(mx, red[i]);
    __syncthreads();

    float sum = 0.f;
#pragma unroll
    for (int i = 0; i < 8; i++) {
        v[i] = expf(v[i] - mx);
        sum += v[i];
    }
#pragma unroll
    for (int o = 16; o > 0; o >>= 1)
        sum += __shfl_xor_sync(0xffffffffu, sum, o);
    if ((tid & 31) == 0) red[tid >> 5] = sum;
    __syncthreads();
    sum = 0.f;
#pragma unroll
    for (int i = 0; i < 8; i++) sum += red[i];
    const float inv = 1.f / sum;

    float w[8];
    *(float4*)&w[0] = *(const float4*)(ir + base);
    *(float4*)&w[4] = *(const float4*)(ir + base + 4);

    uint4 out;
    out.x = pack_h2(__float2half(v[0]*inv + w[0]), __float2half(v[1]*inv + w[1]));
    out.y = pack_h2(__float2half(v[2]*inv + w[2]), __float2half(v[3]*inv + w[3]));
    out.z = pack_h2(__float2half(v[4]*inv + w[4]), __float2half(v[5]*inv + w[5]));
    out.w = pack_h2(__float2half(v[6]*inv + w[6]), __float2half(v[7]*inv + w[7]));
    *(uint4*)(P + row * SEQ + base) = out;
}

// ------------------------- launch -------------------------
extern "C" void kernel_launch(void* const* d_in, const int* in_sizes, int n_in,
                              void* d_out, int out_size)
{
    const float* X  = (const float*)d_in[0];
    const float* I  = (const float*)d_in[1];
    const float* Wq = (const float*)d_in[2];
    const float* bq = (const float*)d_in[3];
    const float* Wk = (const float*)d_in[4];
    const float* bk = (const float*)d_in[5];
    const float* Wv = (const float*)d_in[6];
    const float* bv = (const float*)d_in[7];
    const float* Wo = (const float*)d_in[8];
    const float* bo = (const float*)d_in[9];
    float* out = (float*)d_out;

    __half *Xh, *Wc, *QKh, *Vth, *Oh, *Ph;
    float *Sc, *bqk;
    cudaGetSymbolAddress((void**)&Xh,  g_Xh);
    cudaGetSymbolAddress((void**)&Wc,  g_Wc);
    cudaGetSymbolAddress((void**)&QKh, g_QKh);
    cudaGetSymbolAddress((void**)&Vth, g_Vth);
    cudaGetSymbolAddress((void**)&Oh,  g_Oh);
    cudaGetSymbolAddress((void**)&Ph,  g_Ph);
    cudaGetSymbolAddress((void**)&Sc,  g_S);
    cudaGetSymbolAddress((void**)&bqk, g_bqk);

    cudaFuncSetAttribute(gemm_fp16<1,1>, cudaFuncAttributeMaxDynamicSharedMemorySize, SMEM_TOTAL);
    cudaFuncSetAttribute(gemm_fp16<1,2>, cudaFuncAttributeMaxDynamicSharedMemorySize, SMEM_TOTAL);
    cudaFuncSetAttribute(gemm_fp16<0,0>, cudaFuncAttributeMaxDynamicSharedMemorySize, SMEM_TOTAL);
    cudaFuncSetAttribute(gemm_fp16<1,0>, cudaFuncAttributeMaxDynamicSharedMemorySize, SMEM_TOTAL);
    cudaFuncSetAttribute(gemm_fp16<0,1>, cudaFuncAttributeMaxDynamicSharedMemorySize, SMEM_TOTAL);

    const int XN4 = BS_ROWS * DMODEL / 4;
    const int WN4 = WSZ / 4;

    // 1. convert inputs; pack Q/K biases (kernel, not memcpy: graph-capture safe)
    conv_f16<<<(XN4 + 255) / 256, 256>>>(X, Xh, XN4);
    conv4_f16<<<dim3((WN4 + 255) / 256, 4), 256>>>(Wq, Wk, Wv, Wo, Wc);
    pack_bias<<<(2 * DMODEL + 255) / 256, 256>>>(bq, bk, bqk);

    dim3 blk(NTHREADS);
    const long long QKS = (long long)BS_ROWS * DMODEL;

    // 2. Q|K = X @ {Wq,Wk}^T + {bq,bk} -> fp16, fused over z
    dim3 gQK(DMODEL / BN, BS_ROWS / BM, 2);  // (8, 64, 2)
    gemm_fp16<1,1><<<gQK, blk, SMEM_TOTAL>>>(
        Xh, DMODEL, 0, Wc, DMODEL, WSZ,
        nullptr, QKh, DMODEL, QKS, DMODEL, 1.f, bqk, DMODEL);
    // 3. V^T = Wv @ X^T + bv(row) -> fp16, Vt[d, b*S+s] ld 8192
    dim3 gV(BS_ROWS / BN, DMODEL / BM, 1);   // (64, 8)
    gemm_fp16<1,2><<<gV, blk, SMEM_TOTAL>>>(
        Wc + 2 * WSZ, DMODEL, 0, Xh, DMODEL, 0,
        nullptr, Vth, BS_ROWS, 0, DMODEL, 1.f, bv, 0);
    // 4. scores = (Q K^T)/32 -> fp32, batched
    dim3 gS(SEQ / BN, SEQ / BM, BATCH);      // (16, 16, 4)
    gemm_fp16<0,0><<<gS, blk, SMEM_TOTAL>>>(
        QKh, DMODEL, (long long)SEQ * DMODEL,
        QKh + QKS, DMODEL, (long long)SEQ * DMODEL,
        Sc, nullptr, SEQ, (long long)SEQ * SEQ,
        DMODEL, 0.03125f, nullptr, 0);
    // 5. attn = softmax + intensity -> single fp16
    softmax_f16<<<BATCH * SEQ, 256>>>(Sc, I, Ph);
    // 6. O = attn @ Vt^T -> fp16, batched (B slice = column offset b*S in Vt)
    dim3 gO(DMODEL / BN, SEQ / BM, BATCH);   // (8, 16, 4)
    gemm_fp16<1,0><<<gO, blk, SMEM_TOTAL>>>(
        Ph, SEQ, (long long)SEQ * SEQ,
        Vth, BS_ROWS, (long long)SEQ,
        nullptr, Oh, DMODEL, (long long)SEQ * DMODEL,
        SEQ, 1.f, nullptr, 0);
    // 7. out = O @ Wo^T + bo -> fp32
    dim3 gP(DMODEL / BN, BS_ROWS / BM, 1);   // (8, 64)
    gemm_fp16<0,1><<<gP, blk, SMEM_TOTAL>>>(
        Oh, DMODEL, 0, Wc + 3 * WSZ, DMODEL, 0,
        out, nullptr, DMODEL, 0, DMODEL, 1.f, bo, 0);
}